// round 3
// baseline (speedup 1.0000x reference)
#include <cuda_runtime.h>
#include <cuda_bf16.h>
#include <cstdint>

// Problem constants
#define N_BANDS    128
#define RESO       64
#define N_FRAMES   128
#define N_SAMPLES  32768
#define BATCH      16
#define N_ROWS     (BATCH * N_BANDS)     // 2048 rows (b*128 + c)

typedef unsigned long long u64;

// Intermediate frames buffer, layout [f][b*128+c]
__device__ float g_frames[N_FRAMES * N_ROWS];

__device__ __forceinline__ u64 fma2(u64 a, u64 b, u64 c) {
    u64 d;
    asm("fma.rn.f32x2 %0, %1, %2, %3;" : "=l"(d) : "l"(a), "l"(b), "l"(c));
    return d;
}
__device__ __forceinline__ float u64lo(u64 v) {
    return __uint_as_float((unsigned int)(v & 0xFFFFFFFFull));
}
__device__ __forceinline__ float u64hi(u64 v) {
    return __uint_as_float((unsigned int)(v >> 32));
}

// ---------------------------------------------------------------------------
// Kernel 1: frames[f][row] = sum_r softmax(x[row,:])[r] * resonance[r,f]
// ---------------------------------------------------------------------------
__global__ __launch_bounds__(256)
void frames_kernel(const float* __restrict__ x,
                   const float* __restrict__ reso) {
    __shared__ float res_s[RESO][N_FRAMES];
    __shared__ float xs[16][RESO];
    __shared__ float ps[16][RESO + 1];

    const int tid = threadIdx.x;
    const int rowbase = blockIdx.x * 16;

    for (int idx = tid; idx < RESO * N_FRAMES; idx += 256)
        res_s[idx >> 7][idx & 127] = reso[idx];
    {
        const float* xb = x + rowbase * RESO;
        for (int idx = tid; idx < 16 * RESO; idx += 256)
            xs[idx >> 6][idx & 63] = xb[idx];
    }
    __syncthreads();

    {
        const int w = tid >> 5;
        const int lane = tid & 31;
        #pragma unroll
        for (int rr = 0; rr < 2; ++rr) {
            const int row = w * 2 + rr;
            float v0 = xs[row][lane];
            float v1 = xs[row][lane + 32];
            float m = fmaxf(v0, v1);
            #pragma unroll
            for (int off = 16; off > 0; off >>= 1)
                m = fmaxf(m, __shfl_xor_sync(0xFFFFFFFFu, m, off));
            float e0 = __expf(v0 - m);
            float e1 = __expf(v1 - m);
            float s = e0 + e1;
            #pragma unroll
            for (int off = 16; off > 0; off >>= 1)
                s += __shfl_xor_sync(0xFFFFFFFFu, s, off);
            float inv = 1.0f / s;
            ps[row][lane]      = e0 * inv;
            ps[row][lane + 32] = e1 * inv;
        }
    }
    __syncthreads();

    {
        const int row_l = tid & 15;
        const int f0 = tid >> 4;
        float acc[8];
        #pragma unroll
        for (int i = 0; i < 8; ++i) acc[i] = 0.0f;
        #pragma unroll 4
        for (int r = 0; r < RESO; ++r) {
            const float pv = ps[row_l][r];
            #pragma unroll
            for (int i = 0; i < 8; ++i)
                acc[i] = fmaf(pv, res_s[r][f0 + 16 * i], acc[i]);
        }
        const int grow = rowbase + row_l;
        #pragma unroll
        for (int i = 0; i < 8; ++i)
            g_frames[(f0 + 16 * i) * N_ROWS + grow] = acc[i];
    }
}

// ---------------------------------------------------------------------------
// Kernel 2: 512 blocks x 256 threads. Block n covers samples [64n, 64n+64),
// all 16 batches. Thread: col = tid&15 (4 samples), b = tid>>4 (1 batch).
// Frame pair uniform per block: i0 = (n<2) ? 0 : (n-2)>>2.
// smem holds PRE-DUPLICATED frame values as u64 (v,v) so the hot loop is
// pure LDS.64 + LDG.128 + fma.rn.f32x2 with zero packing MOVs.
// 3-buffer rotating pipeline, prefetch distance = 2 chunks (8 bands).
// ---------------------------------------------------------------------------
__global__ __launch_bounds__(256, 3)
void mix_kernel(const float* __restrict__ fb,
                float* __restrict__ out) {
    __shared__ u64 dup0[N_ROWS];   // 16 KB: (f_i0, f_i0) per (b,c)
    __shared__ u64 dup1[N_ROWS];   // 16 KB: (f_i1, f_i1) per (b,c)

    const int tid = threadIdx.x;
    const int n = blockIdx.x;

    const int i0 = (n < 2) ? 0 : ((n - 2) >> 2);
    const int i1 = (i0 + 1 < N_FRAMES) ? i0 + 1 : N_FRAMES - 1;

    {
        const float* f0p = g_frames + i0 * N_ROWS;
        const float* f1p = g_frames + i1 * N_ROWS;
        #pragma unroll
        for (int k = 0; k < N_ROWS / 256; ++k) {
            const int i = tid + k * 256;
            const float a = f0p[i];
            const float b = f1p[i];
            dup0[i] = ((u64)__float_as_uint(a) << 32) | __float_as_uint(a);
            dup1[i] = ((u64)__float_as_uint(b) << 32) | __float_as_uint(b);
        }
    }
    __syncthreads();

    const int col = tid & 15;               // 4-sample column within block
    const int b   = tid >> 4;               // batch 0..15
    const int s0  = n * 64 + col * 4;

    // Interp weights (align_corners=False), uniform floor == i0 per block.
    float w[4];
    #pragma unroll
    for (int j = 0; j < 4; ++j) {
        float pos = (float)(s0 + j) * (1.0f / 256.0f) + (0.5f / 256.0f - 0.5f);
        pos = fminf(fmaxf(pos, 0.0f), 127.0f);
        w[j] = pos - floorf(pos);
    }

    const u64* __restrict__ P0 = dup0 + b * N_BANDS;
    const u64* __restrict__ P1 = dup1 + b * N_BANDS;
    const ulonglong2* __restrict__ fbp =
        reinterpret_cast<const ulonglong2*>(fb + s0);   // band c at fbp[c*8192]

    u64 acc00 = 0, acc01 = 0, acc10 = 0, acc11 = 0;

    ulonglong2 A[4], B[4], C[4];

#define LOADB(BUF, CB)                                        \
    {                                                         \
        _Pragma("unroll")                                     \
        for (int i = 0; i < 4; ++i)                           \
            BUF[i] = fbp[((CB) + i) * (N_SAMPLES / 4)];       \
    }

#define PROCB(BUF, CB)                                        \
    {                                                         \
        _Pragma("unroll")                                     \
        for (int i = 0; i < 4; ++i) {                         \
            const u64 p0 = P0[(CB) + i];                      \
            const u64 p1 = P1[(CB) + i];                      \
            acc00 = fma2(p0, BUF[i].x, acc00);                \
            acc01 = fma2(p0, BUF[i].y, acc01);                \
            acc10 = fma2(p1, BUF[i].x, acc10);                \
            acc11 = fma2(p1, BUF[i].y, acc11);                \
        }                                                     \
    }

    LOADB(A, 0);
    LOADB(B, 4);

    #pragma unroll 1
    for (int j = 0; j < 120; j += 12) {
        LOADB(C, j + 8);  PROCB(A, j);
        LOADB(A, j + 12); PROCB(B, j + 4);
        LOADB(B, j + 16); PROCB(C, j + 8);
    }
    PROCB(A, 120);
    PROCB(B, 124);

#undef LOADB
#undef PROCB

    // Epilogue: v = (a0 + w*(a1-a0)) / 128, coalesced float4 store.
    {
        float v[4];
        const float a00 = u64lo(acc00), a01 = u64hi(acc00);
        const float a02 = u64lo(acc01), a03 = u64hi(acc01);
        const float a10 = u64lo(acc10), a11 = u64hi(acc10);
        const float a12 = u64lo(acc11), a13 = u64hi(acc11);
        v[0] = fmaf(w[0], a10 - a00, a00) * (1.0f / 128.0f);
        v[1] = fmaf(w[1], a11 - a01, a01) * (1.0f / 128.0f);
        v[2] = fmaf(w[2], a12 - a02, a02) * (1.0f / 128.0f);
        v[3] = fmaf(w[3], a13 - a03, a03) * (1.0f / 128.0f);
        *reinterpret_cast<float4*>(out + b * N_SAMPLES + s0) =
            make_float4(v[0], v[1], v[2], v[3]);
    }
}

// ---------------------------------------------------------------------------
extern "C" void kernel_launch(void* const* d_in, const int* in_sizes, int n_in,
                              void* d_out, int out_size) {
    const float* x = nullptr;      // (16,128,64)    = 131072
    const float* reso = nullptr;   // (64,128)       = 8192
    const float* fb = nullptr;     // (1,128,32768)  = 4194304
    for (int i = 0; i < n_in; ++i) {
        if (in_sizes[i] == BATCH * N_BANDS * RESO)      x = (const float*)d_in[i];
        else if (in_sizes[i] == RESO * N_FRAMES)        reso = (const float*)d_in[i];
        else if (in_sizes[i] == N_BANDS * N_SAMPLES)    fb = (const float*)d_in[i];
    }
    float* out = (float*)d_out;

    frames_kernel<<<N_ROWS / 16, 256>>>(x, reso);
    mix_kernel<<<N_SAMPLES / 64, 256>>>(fb, out);
}

// round 4
// speedup vs baseline: 1.0094x; 1.0094x over previous
#include <cuda_runtime.h>
#include <cuda_bf16.h>
#include <cstdint>

// Problem constants
#define N_BANDS    128
#define RESO       64
#define N_FRAMES   128
#define N_SAMPLES  32768
#define BATCH      16
#define N_ROWS     (BATCH * N_BANDS)     // 2048 rows (b*128 + c)

typedef unsigned long long u64;

// Intermediate frames buffer, layout [f][b*128+c]
__device__ float g_frames[N_FRAMES * N_ROWS];

__device__ __forceinline__ u64 fma2(u64 a, u64 b, u64 c) {
    u64 d;
    asm("fma.rn.f32x2 %0, %1, %2, %3;" : "=l"(d) : "l"(a), "l"(b), "l"(c));
    return d;
}
__device__ __forceinline__ u64 dup32(float x) {
    u64 r;
    unsigned int xi = __float_as_uint(x);
    asm("mov.b64 %0, {%1, %1};" : "=l"(r) : "r"(xi));
    return r;
}
__device__ __forceinline__ float u64lo(u64 v) {
    return __uint_as_float((unsigned int)(v & 0xFFFFFFFFull));
}
__device__ __forceinline__ float u64hi(u64 v) {
    return __uint_as_float((unsigned int)(v >> 32));
}

// ---------------------------------------------------------------------------
// Kernel 1: frames[f][row] = sum_r softmax(x[row,:])[r] * resonance[r,f]
// ---------------------------------------------------------------------------
__global__ __launch_bounds__(256)
void frames_kernel(const float* __restrict__ x,
                   const float* __restrict__ reso) {
    __shared__ float res_s[RESO][N_FRAMES];
    __shared__ float xs[16][RESO];
    __shared__ float ps[16][RESO + 1];

    const int tid = threadIdx.x;
    const int rowbase = blockIdx.x * 16;

    for (int idx = tid; idx < RESO * N_FRAMES; idx += 256)
        res_s[idx >> 7][idx & 127] = reso[idx];
    {
        const float* xb = x + rowbase * RESO;
        for (int idx = tid; idx < 16 * RESO; idx += 256)
            xs[idx >> 6][idx & 63] = xb[idx];
    }
    __syncthreads();

    {
        const int w = tid >> 5;
        const int lane = tid & 31;
        #pragma unroll
        for (int rr = 0; rr < 2; ++rr) {
            const int row = w * 2 + rr;
            float v0 = xs[row][lane];
            float v1 = xs[row][lane + 32];
            float m = fmaxf(v0, v1);
            #pragma unroll
            for (int off = 16; off > 0; off >>= 1)
                m = fmaxf(m, __shfl_xor_sync(0xFFFFFFFFu, m, off));
            float e0 = __expf(v0 - m);
            float e1 = __expf(v1 - m);
            float s = e0 + e1;
            #pragma unroll
            for (int off = 16; off > 0; off >>= 1)
                s += __shfl_xor_sync(0xFFFFFFFFu, s, off);
            float inv = 1.0f / s;
            ps[row][lane]      = e0 * inv;
            ps[row][lane + 32] = e1 * inv;
        }
    }
    __syncthreads();

    {
        const int row_l = tid & 15;
        const int f0 = tid >> 4;
        float acc[8];
        #pragma unroll
        for (int i = 0; i < 8; ++i) acc[i] = 0.0f;
        #pragma unroll 4
        for (int r = 0; r < RESO; ++r) {
            const float pv = ps[row_l][r];
            #pragma unroll
            for (int i = 0; i < 8; ++i)
                acc[i] = fmaf(pv, res_s[r][f0 + 16 * i], acc[i]);
        }
        const int grow = rowbase + row_l;
        #pragma unroll
        for (int i = 0; i < 8; ++i)
            g_frames[(f0 + 16 * i) * N_ROWS + grow] = acc[i];
    }
}

// ---------------------------------------------------------------------------
// Kernel 2: grid 512 x 128 threads. Block n = samples [64n, 64n+64),
// all 16 batches, frame pair uniform: i0 = (n<2) ? 0 : (n-2)>>2.
// fb staged GMEM->SMEM with cp.async (4 chunks of 32 bands, 3-buffer ring).
// Warps 0-1 accumulate the F0 dot, warps 2-3 the F1 dot (1 sample/thread,
// 16 batches as 8 f32x2 accs); halves combined via smem in the epilogue.
// Frames transposed in smem as [c][16] so one broadcast LDS.128 feeds two
// batch-pair fma2 ops with zero packing MOVs.
// ---------------------------------------------------------------------------
#define CHUNK_BANDS  32
#define CHUNK_FLOATS (CHUNK_BANDS * 64)   // 2048 floats = 8KB

__global__ __launch_bounds__(128, 5)
void mix_kernel(const float* __restrict__ fb,
                float* __restrict__ out) {
    __shared__ __align__(16) float fbbuf[3][CHUNK_FLOATS];  // 24 KB
    __shared__ __align__(16) float F0s[N_ROWS];             // 8 KB, [c*16+b]
    __shared__ __align__(16) float F1s[N_ROWS];             // 8 KB

    const int tid = threadIdx.x;
    const int n = blockIdx.x;
    const int s_base = n * 64;

    const int i0 = (n < 2) ? 0 : ((n - 2) >> 2);
    const int i1 = (i0 + 1 < N_FRAMES) ? i0 + 1 : N_FRAMES - 1;

    // --- stage fb chunk (32 bands x 64 samples) via cp.async; 4x16B/thread ---
#define STAGE(CHUNK, BUF)                                                     \
    {                                                                         \
        _Pragma("unroll")                                                     \
        for (int i = 0; i < 4; ++i) {                                         \
            const int o = (i * 128 + tid) * 16;   /* byte off in chunk */     \
            const int band = o >> 8;              /* 256B per band row */     \
            const int within = o & 255;                                       \
            const float* g = fb + ((CHUNK) * CHUNK_BANDS + band) * N_SAMPLES  \
                               + s_base + (within >> 2);                      \
            unsigned int saddr = (unsigned int)__cvta_generic_to_shared(      \
                &fbbuf[BUF][0]) + o;                                          \
            asm volatile("cp.async.ca.shared.global [%0], [%1], 16;\n"        \
                         :: "r"(saddr), "l"(g));                              \
        }                                                                     \
        asm volatile("cp.async.commit_group;\n");                             \
    }

    // Kick off first three chunks immediately.
    STAGE(0, 0);
    STAGE(1, 1);
    STAGE(2, 2);

    // Stage frames transposed: F[c*16+b] = g_frames[f][b*128+c]. (L2-hot.)
    {
        const float* f0p = g_frames + i0 * N_ROWS;
        const float* f1p = g_frames + i1 * N_ROWS;
        #pragma unroll
        for (int k = 0; k < 16; ++k) {
            const int j = tid + 128 * k;     // j = c*16 + b
            const int c = j >> 4;
            const int b = j & 15;
            F0s[j] = f0p[b * 128 + c];
            F1s[j] = f1p[b * 128 + c];
        }
    }

    const int col = tid & 63;                         // sample within block
    const float* __restrict__ Fs = (tid < 64) ? F0s : F1s;   // warp-uniform

    u64 acc[8];
    #pragma unroll
    for (int p = 0; p < 8; ++p) acc[p] = 0ull;

#define PROCESS(BUF, CBASE)                                                   \
    {                                                                         \
        _Pragma("unroll 8")                                                   \
        for (int cl = 0; cl < CHUNK_BANDS; ++cl) {                            \
            const float fbv = fbbuf[BUF][cl * 64 + col];                      \
            const u64 d = dup32(fbv);                                         \
            const ulonglong2* __restrict__ q =                                \
                reinterpret_cast<const ulonglong2*>(Fs + ((CBASE) + cl) * 16);\
            _Pragma("unroll")                                                 \
            for (int qi = 0; qi < 2; ++qi) {                                  \
                const ulonglong2 v = q[qi];                                   \
                acc[4 * qi + 0] = fma2(v.x, d, acc[4 * qi + 0]);              \
                acc[4 * qi + 1] = fma2(v.y, d, acc[4 * qi + 1]);              \
            }                                                                 \
            const ulonglong2 v2 = q[0 + 2];                                   \
            /* unreachable filler removed */                                  \
            (void)v2;                                                         \
        }                                                                     \
    }

    // NOTE: the quad loop above covers 8 of 16 batches; do it properly below.
#undef PROCESS
#define PROCESS(BUF, CBASE)                                                   \
    {                                                                         \
        _Pragma("unroll 8")                                                   \
        for (int cl = 0; cl < CHUNK_BANDS; ++cl) {                            \
            const float fbv = fbbuf[BUF][cl * 64 + col];                      \
            const u64 d = dup32(fbv);                                         \
            const ulonglong2* __restrict__ q =                                \
                reinterpret_cast<const ulonglong2*>(Fs + ((CBASE) + cl) * 16);\
            const ulonglong2 va = q[0];   /* batches 0..3  */                 \
            const ulonglong2 vb = q[1];   /* batches 4..7  */                 \
            const ulonglong2 vc = q[2];   /* batches 8..11 */                 \
            const ulonglong2 vd = q[3];   /* batches 12..15*/                 \
            acc[0] = fma2(va.x, d, acc[0]);                                   \
            acc[1] = fma2(va.y, d, acc[1]);                                   \
            acc[2] = fma2(vb.x, d, acc[2]);                                   \
            acc[3] = fma2(vb.y, d, acc[3]);                                   \
            acc[4] = fma2(vc.x, d, acc[4]);                                   \
            acc[5] = fma2(vc.y, d, acc[5]);                                   \
            acc[6] = fma2(vd.x, d, acc[6]);                                   \
            acc[7] = fma2(vd.y, d, acc[7]);                                   \
        }                                                                     \
    }

    // Pipeline: chunks 0..3 over a 3-buffer ring.
    asm volatile("cp.async.wait_group 2;\n" ::: "memory");
    __syncthreads();
    PROCESS(0, 0);
    __syncthreads();            // buf0 free for reuse
    STAGE(3, 0);

    asm volatile("cp.async.wait_group 2;\n" ::: "memory");
    __syncthreads();
    PROCESS(1, 32);

    asm volatile("cp.async.wait_group 1;\n" ::: "memory");
    __syncthreads();
    PROCESS(2, 64);

    asm volatile("cp.async.wait_group 0;\n" ::: "memory");
    __syncthreads();
    PROCESS(0, 96);

#undef STAGE
#undef PROCESS

    // --- Epilogue: combine F0/F1 halves, interpolate, store ---
    __syncthreads();   // everyone done with fbbuf
    u64* comb = reinterpret_cast<u64*>(&fbbuf[0][0]);   // 64 * 9 u64 = 4.5KB
    if (tid >= 64) {
        #pragma unroll
        for (int p = 0; p < 8; ++p)
            comb[(tid - 64) * 9 + p] = acc[p];          // padded stride 9
    }
    __syncthreads();
    if (tid < 64) {
        const int s = s_base + col;
        float pos = (float)s * (1.0f / 256.0f) + (0.5f / 256.0f - 0.5f);
        pos = fminf(fmaxf(pos, 0.0f), 127.0f);
        const float w = pos - floorf(pos);
        #pragma unroll
        for (int p = 0; p < 8; ++p) {
            const u64 a1p = comb[tid * 9 + p];
            const float a0lo = u64lo(acc[p]), a0hi = u64hi(acc[p]);
            const float a1lo = u64lo(a1p),    a1hi = u64hi(a1p);
            out[(2 * p) * N_SAMPLES + s] =
                fmaf(w, a1lo - a0lo, a0lo) * (1.0f / 128.0f);
            out[(2 * p + 1) * N_SAMPLES + s] =
                fmaf(w, a1hi - a0hi, a0hi) * (1.0f / 128.0f);
        }
    }
}

// ---------------------------------------------------------------------------
extern "C" void kernel_launch(void* const* d_in, const int* in_sizes, int n_in,
                              void* d_out, int out_size) {
    const float* x = nullptr;      // (16,128,64)    = 131072
    const float* reso = nullptr;   // (64,128)       = 8192
    const float* fb = nullptr;     // (1,128,32768)  = 4194304
    for (int i = 0; i < n_in; ++i) {
        if (in_sizes[i] == BATCH * N_BANDS * RESO)      x = (const float*)d_in[i];
        else if (in_sizes[i] == RESO * N_FRAMES)        reso = (const float*)d_in[i];
        else if (in_sizes[i] == N_BANDS * N_SAMPLES)    fb = (const float*)d_in[i];
    }
    float* out = (float*)d_out;

    frames_kernel<<<N_ROWS / 16, 256>>>(x, reso);
    mix_kernel<<<N_SAMPLES / 64, 128>>>(fb, out);
}

// round 5
// speedup vs baseline: 1.0808x; 1.0707x over previous
#include <cuda_runtime.h>
#include <cuda_bf16.h>
#include <cstdint>

#define N_BANDS    128
#define RESO       64
#define N_FRAMES   128
#define N_SAMPLES  32768
#define BATCH      16
#define N_ROWS     (BATCH * N_BANDS)

typedef unsigned long long u64;

// Pre-duplicated frames: g_framesd[f*2048 + c*16 + b] = (v, v) packed in u64.
__device__ u64 g_framesd[N_FRAMES * N_ROWS];

__device__ __forceinline__ u64 fma2(u64 a, u64 b, u64 c) {
    u64 d;
    asm("fma.rn.f32x2 %0, %1, %2, %3;" : "=l"(d) : "l"(a), "l"(b), "l"(c));
    return d;
}
__device__ __forceinline__ float u64lo(u64 v) {
    return __uint_as_float((unsigned int)(v & 0xFFFFFFFFull));
}
__device__ __forceinline__ float u64hi(u64 v) {
    return __uint_as_float((unsigned int)(v >> 32));
}

// ---------------------------------------------------------------------------
// Kernel 1: frames = softmax(x) @ resonance, stored transposed + duplicated:
//   g_framesd[f][c][b] = (v,v) u64,  v = frames[b,c,f]
// ---------------------------------------------------------------------------
__global__ __launch_bounds__(256)
void frames_kernel(const float* __restrict__ x,
                   const float* __restrict__ reso) {
    __shared__ float res_s[RESO][N_FRAMES];
    __shared__ float xs[16][RESO];
    __shared__ float ps[16][RESO + 1];

    const int tid = threadIdx.x;
    const int rowbase = blockIdx.x * 16;

    for (int idx = tid; idx < RESO * N_FRAMES; idx += 256)
        res_s[idx >> 7][idx & 127] = reso[idx];
    {
        const float* xb = x + rowbase * RESO;
        for (int idx = tid; idx < 16 * RESO; idx += 256)
            xs[idx >> 6][idx & 63] = xb[idx];
    }
    __syncthreads();

    {
        const int w = tid >> 5;
        const int lane = tid & 31;
        #pragma unroll
        for (int rr = 0; rr < 2; ++rr) {
            const int row = w * 2 + rr;
            float v0 = xs[row][lane];
            float v1 = xs[row][lane + 32];
            float m = fmaxf(v0, v1);
            #pragma unroll
            for (int off = 16; off > 0; off >>= 1)
                m = fmaxf(m, __shfl_xor_sync(0xFFFFFFFFu, m, off));
            float e0 = __expf(v0 - m);
            float e1 = __expf(v1 - m);
            float s = e0 + e1;
            #pragma unroll
            for (int off = 16; off > 0; off >>= 1)
                s += __shfl_xor_sync(0xFFFFFFFFu, s, off);
            float inv = 1.0f / s;
            ps[row][lane]      = e0 * inv;
            ps[row][lane + 32] = e1 * inv;
        }
    }
    __syncthreads();

    {
        const int row_l = tid & 15;
        const int f0 = tid >> 4;
        float acc[8];
        #pragma unroll
        for (int i = 0; i < 8; ++i) acc[i] = 0.0f;
        #pragma unroll 4
        for (int r = 0; r < RESO; ++r) {
            const float pv = ps[row_l][r];
            #pragma unroll
            for (int i = 0; i < 8; ++i)
                acc[i] = fmaf(pv, res_s[r][f0 + 16 * i], acc[i]);
        }
        const int grow = rowbase + row_l;          // row = b*128 + c
        const int b = grow >> 7;
        const int c = grow & 127;
        #pragma unroll
        for (int i = 0; i < 8; ++i) {
            const unsigned int vi = __float_as_uint(acc[i]);
            g_framesd[(f0 + 16 * i) * N_ROWS + c * 16 + b] =
                ((u64)vi << 32) | vi;
        }
    }
}

// ---------------------------------------------------------------------------
// Kernel 2: 512 blocks x 128 threads. Block n = samples [64n, 64n+64).
// Frame pair uniform per block: i0 = (n<2) ? 0 : (n-2)>>2.
// Thread: sg = tid&15 (4 samples), bh = (tid>>4)&3 (4 batches), ih = tid>>6
// (F0-dot or F1-dot half). fb + dup'd frames staged via cp.async.
// Hot loop per band: 1 LDS.128 (fb) + 2 LDS.128 (frames) + 8 fma2, no MOVs.
// ---------------------------------------------------------------------------
#define CH_FLOATS 1024      // 16 bands x 64 samples per chunk (4KB)

__global__ __launch_bounds__(128)
void mix_kernel(const float* __restrict__ fb,
                float* __restrict__ out) {
    __shared__ __align__(16) float fbbuf[3 * CH_FLOATS];   // 12 KB ring
    __shared__ __align__(16) u64 F0d[N_ROWS];              // 16 KB [c*16+b]
    __shared__ __align__(16) u64 F1d[N_ROWS];              // 16 KB

    const int tid = threadIdx.x;
    const int n = blockIdx.x;
    const int s_base = n * 64;

    const int i0 = (n < 2) ? 0 : ((n - 2) >> 2);
    const int i1 = (i0 + 1 < N_FRAMES) ? i0 + 1 : N_FRAMES - 1;

    const unsigned int fb_s0 =
        (unsigned int)__cvta_generic_to_shared(&fbbuf[0]);
    const unsigned int F0_s0 =
        (unsigned int)__cvta_generic_to_shared(&F0d[0]);
    const unsigned int F1_s0 =
        (unsigned int)__cvta_generic_to_shared(&F1d[0]);

#define STAGE_FB(CHUNK, BUF)                                                  \
    {                                                                         \
        _Pragma("unroll")                                                     \
        for (int i = 0; i < 2; ++i) {                                         \
            const int o = (i * 128 + tid) * 16;                               \
            const int band = o >> 8;                                          \
            const int within = o & 255;                                       \
            const float* g = fb + ((CHUNK) * 16 + band) * N_SAMPLES           \
                               + s_base + (within >> 2);                      \
            asm volatile("cp.async.ca.shared.global [%0], [%1], 16;\n"        \
                         :: "r"(fb_s0 + (BUF) * 4096 + o), "l"(g));           \
        }                                                                     \
        asm volatile("cp.async.commit_group;\n");                             \
    }

    // Group 0: frames (both) + fb chunk 0. Groups 1,2: chunks 1,2.
    {
        const char* g0 = (const char*)(g_framesd + i0 * N_ROWS);
        const char* g1 = (const char*)(g_framesd + i1 * N_ROWS);
        #pragma unroll
        for (int i = 0; i < 8; ++i) {
            const int o = (i * 128 + tid) * 16;
            asm volatile("cp.async.ca.shared.global [%0], [%1], 16;\n"
                         :: "r"(F0_s0 + o), "l"(g0 + o));
            asm volatile("cp.async.ca.shared.global [%0], [%1], 16;\n"
                         :: "r"(F1_s0 + o), "l"(g1 + o));
        }
    }
    STAGE_FB(0, 0);
    STAGE_FB(1, 1);
    STAGE_FB(2, 2);

    const int sg = tid & 15;             // sample group (4 samples)
    const int bh = (tid >> 4) & 3;       // batch group (4 batches)
    const int ih = tid >> 6;             // 0: F0 dot, 1: F1 dot
    const int b0 = bh * 4;
    const u64* __restrict__ Fd = ih ? F1d : F0d;   // warp-uniform

    u64 acc[8];   // acc[jb*2+p]: batch b0+jb, sample pair p
    #pragma unroll
    for (int p = 0; p < 8; ++p) acc[p] = 0ull;

#define PROC(BUF, CBASE)                                                      \
    {                                                                         \
        _Pragma("unroll")                                                     \
        for (int cl = 0; cl < 16; ++cl) {                                     \
            const ulonglong2 fbp = *reinterpret_cast<const ulonglong2*>(      \
                &fbbuf[(BUF) * CH_FLOATS + cl * 64 + sg * 4]);                \
            const u64* Frow = Fd + ((CBASE) + cl) * 16 + b0;                  \
            const ulonglong2 va =                                             \
                *reinterpret_cast<const ulonglong2*>(Frow);                   \
            const ulonglong2 vb =                                             \
                *reinterpret_cast<const ulonglong2*>(Frow + 2);               \
            acc[0] = fma2(va.x, fbp.x, acc[0]);                               \
            acc[1] = fma2(va.x, fbp.y, acc[1]);                               \
            acc[2] = fma2(va.y, fbp.x, acc[2]);                               \
            acc[3] = fma2(va.y, fbp.y, acc[3]);                               \
            acc[4] = fma2(vb.x, fbp.x, acc[4]);                               \
            acc[5] = fma2(vb.x, fbp.y, acc[5]);                               \
            acc[6] = fma2(vb.y, fbp.x, acc[6]);                               \
            acc[7] = fma2(vb.y, fbp.y, acc[7]);                               \
        }                                                                     \
    }

#define WAITG(N) asm volatile("cp.async.wait_group %0;\n" :: "n"(N) : "memory")

    WAITG(2); __syncthreads(); PROC(0, 0);   __syncthreads(); STAGE_FB(3, 0);
    WAITG(2); __syncthreads(); PROC(1, 16);  __syncthreads(); STAGE_FB(4, 1);
    WAITG(2); __syncthreads(); PROC(2, 32);  __syncthreads(); STAGE_FB(5, 2);
    WAITG(2); __syncthreads(); PROC(0, 48);  __syncthreads(); STAGE_FB(6, 0);
    WAITG(2); __syncthreads(); PROC(1, 64);  __syncthreads(); STAGE_FB(7, 1);
    WAITG(2); __syncthreads(); PROC(2, 80);
    WAITG(1); __syncthreads(); PROC(0, 96);
    WAITG(0); __syncthreads(); PROC(1, 112);

#undef STAGE_FB
#undef PROC
#undef WAITG

    // --- Epilogue: F1-half passes accs through smem; F0-half combines ---
    __syncthreads();
    u64* comb = reinterpret_cast<u64*>(&fbbuf[0]);   // 64*9 u64 = 4.5KB
    if (tid >= 64) {
        const int j = tid - 64;
        #pragma unroll
        for (int p = 0; p < 8; ++p) comb[j * 9 + p] = acc[p];
    }
    __syncthreads();
    if (tid < 64) {
        const int s0 = s_base + sg * 4;
        float w[4];
        #pragma unroll
        for (int j = 0; j < 4; ++j) {
            float pos = (float)(s0 + j) * (1.0f / 256.0f)
                        + (0.5f / 256.0f - 0.5f);
            pos = fminf(fmaxf(pos, 0.0f), 127.0f);
            w[j] = pos - floorf(pos);
        }
        #pragma unroll
        for (int jb = 0; jb < 4; ++jb) {
            const u64 a0p0 = acc[jb * 2 + 0];
            const u64 a0p1 = acc[jb * 2 + 1];
            const u64 a1p0 = comb[tid * 9 + jb * 2 + 0];
            const u64 a1p1 = comb[tid * 9 + jb * 2 + 1];
            float4 o;
            o.x = fmaf(w[0], u64lo(a1p0) - u64lo(a0p0), u64lo(a0p0)) * (1.0f / 128.0f);
            o.y = fmaf(w[1], u64hi(a1p0) - u64hi(a0p0), u64hi(a0p0)) * (1.0f / 128.0f);
            o.z = fmaf(w[2], u64lo(a1p1) - u64lo(a0p1), u64lo(a0p1)) * (1.0f / 128.0f);
            o.w = fmaf(w[3], u64hi(a1p1) - u64hi(a0p1), u64hi(a0p1)) * (1.0f / 128.0f);
            *reinterpret_cast<float4*>(out + (b0 + jb) * N_SAMPLES + s0) = o;
        }
    }
}

// ---------------------------------------------------------------------------
extern "C" void kernel_launch(void* const* d_in, const int* in_sizes, int n_in,
                              void* d_out, int out_size) {
    const float* x = nullptr;      // (16,128,64)    = 131072
    const float* reso = nullptr;   // (64,128)       = 8192
    const float* fb = nullptr;     // (1,128,32768)  = 4194304
    for (int i = 0; i < n_in; ++i) {
        if (in_sizes[i] == BATCH * N_BANDS * RESO)      x = (const float*)d_in[i];
        else if (in_sizes[i] == RESO * N_FRAMES)        reso = (const float*)d_in[i];
        else if (in_sizes[i] == N_BANDS * N_SAMPLES)    fb = (const float*)d_in[i];
    }
    float* out = (float*)d_out;

    frames_kernel<<<N_ROWS / 16, 256>>>(x, reso);
    mix_kernel<<<N_SAMPLES / 64, 128>>>(fb, out);
}

// round 6
// speedup vs baseline: 1.1758x; 1.0879x over previous
#include <cuda_runtime.h>
#include <cuda_bf16.h>
#include <cstdint>

#define N_BANDS    128
#define RESO       64
#define N_FRAMES   128
#define N_SAMPLES  32768
#define BATCH      16
#define N_ROWS     (BATCH * N_BANDS)

typedef unsigned long long u64;

// Pre-duplicated frames: g_framesd[f*2048 + c*16 + b] = (v, v) packed in u64.
__device__ u64 g_framesd[N_FRAMES * N_ROWS];

__device__ __forceinline__ u64 fma2(u64 a, u64 b, u64 c) {
    u64 d;
    asm("fma.rn.f32x2 %0, %1, %2, %3;" : "=l"(d) : "l"(a), "l"(b), "l"(c));
    return d;
}
__device__ __forceinline__ u64 add2(u64 a, u64 b) {
    u64 d;
    asm("add.rn.f32x2 %0, %1, %2;" : "=l"(d) : "l"(a), "l"(b));
    return d;
}
__device__ __forceinline__ float u64lo(u64 v) {
    return __uint_as_float((unsigned int)(v & 0xFFFFFFFFull));
}
__device__ __forceinline__ float u64hi(u64 v) {
    return __uint_as_float((unsigned int)(v >> 32));
}

// ---------------------------------------------------------------------------
// Kernel 1: frames = softmax(x) @ resonance, stored transposed + duplicated:
//   g_framesd[f][c][b] = (v,v) u64,  v = frames[b,c,f]
// ---------------------------------------------------------------------------
__global__ __launch_bounds__(256)
void frames_kernel(const float* __restrict__ x,
                   const float* __restrict__ reso) {
    __shared__ float res_s[RESO][N_FRAMES];
    __shared__ float xs[16][RESO];
    __shared__ float ps[16][RESO + 1];

    const int tid = threadIdx.x;
    const int rowbase = blockIdx.x * 16;

    for (int idx = tid; idx < RESO * N_FRAMES; idx += 256)
        res_s[idx >> 7][idx & 127] = reso[idx];
    {
        const float* xb = x + rowbase * RESO;
        for (int idx = tid; idx < 16 * RESO; idx += 256)
            xs[idx >> 6][idx & 63] = xb[idx];
    }
    __syncthreads();

    {
        const int w = tid >> 5;
        const int lane = tid & 31;
        #pragma unroll
        for (int rr = 0; rr < 2; ++rr) {
            const int row = w * 2 + rr;
            float v0 = xs[row][lane];
            float v1 = xs[row][lane + 32];
            float m = fmaxf(v0, v1);
            #pragma unroll
            for (int off = 16; off > 0; off >>= 1)
                m = fmaxf(m, __shfl_xor_sync(0xFFFFFFFFu, m, off));
            float e0 = __expf(v0 - m);
            float e1 = __expf(v1 - m);
            float s = e0 + e1;
            #pragma unroll
            for (int off = 16; off > 0; off >>= 1)
                s += __shfl_xor_sync(0xFFFFFFFFu, s, off);
            float inv = 1.0f / s;
            ps[row][lane]      = e0 * inv;
            ps[row][lane + 32] = e1 * inv;
        }
    }
    __syncthreads();

    {
        const int row_l = tid & 15;
        const int f0 = tid >> 4;
        float acc[8];
        #pragma unroll
        for (int i = 0; i < 8; ++i) acc[i] = 0.0f;
        #pragma unroll 4
        for (int r = 0; r < RESO; ++r) {
            const float pv = ps[row_l][r];
            #pragma unroll
            for (int i = 0; i < 8; ++i)
                acc[i] = fmaf(pv, res_s[r][f0 + 16 * i], acc[i]);
        }
        const int grow = rowbase + row_l;          // row = b*128 + c
        const int b = grow >> 7;
        const int c = grow & 127;
        #pragma unroll
        for (int i = 0; i < 8; ++i) {
            const unsigned int vi = __float_as_uint(acc[i]);
            g_framesd[(f0 + 16 * i) * N_ROWS + c * 16 + b] =
                ((u64)vi << 32) | vi;
        }
    }
}

// ---------------------------------------------------------------------------
// Kernel 2: 512 blocks x 256 threads. Block n = samples [64n, 64n+64).
// Frame pair uniform per block: i0 = (n<2) ? 0 : (n-2)>>2.
// All data staged upfront in ONE cp.async group: fb tile (128 bands x 64
// samples, 32KB) + F0d/F1d dup'd tables (32KB). Single wait + sync, then a
// barrier-free hot loop.
// Thread (sg = tid&15: 4 samples, bh = bit4: 8 batches, ih = bit5: F0/F1,
// bs = bits6-7: 32-band slice): 16 u64 accs.
// Per band: 1 LDS.128 fb + 4 LDS.128 frames + 16 fma2 (21 issues / 16 fma2).
// Epilogue: smem reduce over (ih, bs), interp, STG.128.
// ---------------------------------------------------------------------------
__global__ __launch_bounds__(256, 3)
void mix_kernel(const float* __restrict__ fb,
                float* __restrict__ out) {
    __shared__ __align__(16) float fbT[N_BANDS * 64];   // 32 KB [c][64]
    __shared__ __align__(16) u64 F0d[N_ROWS];           // 16 KB [c*16+b]
    __shared__ __align__(16) u64 F1d[N_ROWS];           // 16 KB

    const int tid = threadIdx.x;
    const int n = blockIdx.x;
    const int s_base = n * 64;

    const int i0 = (n < 2) ? 0 : ((n - 2) >> 2);
    const int i1 = (i0 + 1 < N_FRAMES) ? i0 + 1 : N_FRAMES - 1;

    const unsigned int fb_s0 = (unsigned int)__cvta_generic_to_shared(&fbT[0]);
    const unsigned int F0_s0 = (unsigned int)__cvta_generic_to_shared(&F0d[0]);
    const unsigned int F1_s0 = (unsigned int)__cvta_generic_to_shared(&F1d[0]);

    // --- Stage EVERYTHING in one group ---
    {
        // fb tile: 32KB, 8 x 16B per thread. 256B per band row.
        #pragma unroll
        for (int i = 0; i < 8; ++i) {
            const int o = (i * 256 + tid) * 16;
            const int band = o >> 8;
            const int within = o & 255;
            const float* g = fb + band * N_SAMPLES + s_base + (within >> 2);
            asm volatile("cp.async.ca.shared.global [%0], [%1], 16;\n"
                         :: "r"(fb_s0 + o), "l"(g));
        }
        // frames tables: 16KB each, 4 x 16B per thread each.
        const char* g0 = (const char*)(g_framesd + i0 * N_ROWS);
        const char* g1 = (const char*)(g_framesd + i1 * N_ROWS);
        #pragma unroll
        for (int i = 0; i < 4; ++i) {
            const int o = (i * 256 + tid) * 16;
            asm volatile("cp.async.ca.shared.global [%0], [%1], 16;\n"
                         :: "r"(F0_s0 + o), "l"(g0 + o));
            asm volatile("cp.async.ca.shared.global [%0], [%1], 16;\n"
                         :: "r"(F1_s0 + o), "l"(g1 + o));
        }
        asm volatile("cp.async.commit_group;\n");
        asm volatile("cp.async.wait_group 0;\n" ::: "memory");
    }
    __syncthreads();

    const int sg = tid & 15;             // 4-sample group
    const int bh = (tid >> 4) & 1;       // batch octet (0..7 / 8..15)
    const int ih = (tid >> 5) & 1;       // 0: F0 dot, 1: F1 dot
    const int bs = tid >> 6;             // band slice (32 bands)
    const u64* __restrict__ Fd = ih ? F1d : F0d;   // warp-uniform

    u64 acc[16];   // acc[jb*2+p]: batch bh*8+jb, sample pair p
    #pragma unroll
    for (int p = 0; p < 16; ++p) acc[p] = 0ull;

    const int cbase = bs * 32;
    #pragma unroll 4
    for (int cl = 0; cl < 32; ++cl) {
        const int c = cbase + cl;
        const ulonglong2 fp =
            *reinterpret_cast<const ulonglong2*>(&fbT[c * 64 + sg * 4]);
        const u64* Fr = Fd + c * 16 + bh * 8;
        const ulonglong2 va = *reinterpret_cast<const ulonglong2*>(Fr);
        const ulonglong2 vb = *reinterpret_cast<const ulonglong2*>(Fr + 2);
        const ulonglong2 vc = *reinterpret_cast<const ulonglong2*>(Fr + 4);
        const ulonglong2 vd = *reinterpret_cast<const ulonglong2*>(Fr + 6);
        acc[0]  = fma2(va.x, fp.x, acc[0]);
        acc[1]  = fma2(va.x, fp.y, acc[1]);
        acc[2]  = fma2(va.y, fp.x, acc[2]);
        acc[3]  = fma2(va.y, fp.y, acc[3]);
        acc[4]  = fma2(vb.x, fp.x, acc[4]);
        acc[5]  = fma2(vb.x, fp.y, acc[5]);
        acc[6]  = fma2(vb.y, fp.x, acc[6]);
        acc[7]  = fma2(vb.y, fp.y, acc[7]);
        acc[8]  = fma2(vc.x, fp.x, acc[8]);
        acc[9]  = fma2(vc.x, fp.y, acc[9]);
        acc[10] = fma2(vc.y, fp.x, acc[10]);
        acc[11] = fma2(vc.y, fp.y, acc[11]);
        acc[12] = fma2(vd.x, fp.x, acc[12]);
        acc[13] = fma2(vd.x, fp.y, acc[13]);
        acc[14] = fma2(vd.y, fp.x, acc[14]);
        acc[15] = fma2(vd.y, fp.y, acc[15]);
    }

    // --- Epilogue: reduce over (ih, bs) via smem scratch (reuse fbT) ---
    __syncthreads();   // everyone done reading fbT
    u64* S = reinterpret_cast<u64*>(&fbT[0]);  // 4096 u64 = 32KB
    // S[(((ih*4+bs)*2+bh)*8 + jb)*2 + p][16] + sg
    {
        const int slot = (ih * 4 + bs) * 2 + bh;
        #pragma unroll
        for (int jb = 0; jb < 8; ++jb) {
            #pragma unroll
            for (int p = 0; p < 2; ++p)
                S[(((slot * 8 + jb) * 2) + p) * 16 + sg] = acc[jb * 2 + p];
        }
    }
    __syncthreads();

    if (tid < 64) {
        const int e_sg = tid & 15;
        const int e_bq = tid >> 4;           // batch quad (4 batches)
        const int s0 = s_base + e_sg * 4;

        float w[4];
        #pragma unroll
        for (int j = 0; j < 4; ++j) {
            float pos = (float)(s0 + j) * (1.0f / 256.0f)
                        + (0.5f / 256.0f - 0.5f);
            pos = fminf(fmaxf(pos, 0.0f), 127.0f);
            w[j] = pos - floorf(pos);
        }

        #pragma unroll
        for (int jj = 0; jj < 4; ++jj) {
            const int b  = e_bq * 4 + jj;
            const int bh_ = b >> 3;
            const int jb  = b & 7;
            float v[4];
            #pragma unroll
            for (int p = 0; p < 2; ++p) {
                u64 A0 = 0ull, A1 = 0ull;
                #pragma unroll
                for (int bsx = 0; bsx < 4; ++bsx) {
                    const int sl0 = (0 * 4 + bsx) * 2 + bh_;
                    const int sl1 = (1 * 4 + bsx) * 2 + bh_;
                    A0 = add2(A0, S[((sl0 * 8 + jb) * 2 + p) * 16 + e_sg]);
                    A1 = add2(A1, S[((sl1 * 8 + jb) * 2 + p) * 16 + e_sg]);
                }
                const float a0l = u64lo(A0), a0h = u64hi(A0);
                const float a1l = u64lo(A1), a1h = u64hi(A1);
                v[2 * p + 0] = fmaf(w[2 * p + 0], a1l - a0l, a0l) * (1.0f / 128.0f);
                v[2 * p + 1] = fmaf(w[2 * p + 1], a1h - a0h, a0h) * (1.0f / 128.0f);
            }
            *reinterpret_cast<float4*>(out + b * N_SAMPLES + s0) =
                make_float4(v[0], v[1], v[2], v[3]);
        }
    }
}

// ---------------------------------------------------------------------------
extern "C" void kernel_launch(void* const* d_in, const int* in_sizes, int n_in,
                              void* d_out, int out_size) {
    const float* x = nullptr;      // (16,128,64)    = 131072
    const float* reso = nullptr;   // (64,128)       = 8192
    const float* fb = nullptr;     // (1,128,32768)  = 4194304
    for (int i = 0; i < n_in; ++i) {
        if (in_sizes[i] == BATCH * N_BANDS * RESO)      x = (const float*)d_in[i];
        else if (in_sizes[i] == RESO * N_FRAMES)        reso = (const float*)d_in[i];
        else if (in_sizes[i] == N_BANDS * N_SAMPLES)    fb = (const float*)d_in[i];
    }
    float* out = (float*)d_out;

    frames_kernel<<<N_ROWS / 16, 256>>>(x, reso);
    mix_kernel<<<N_SAMPLES / 64, 256>>>(fb, out);
}

// round 7
// speedup vs baseline: 1.1889x; 1.0111x over previous
#include <cuda_runtime.h>
#include <cuda_bf16.h>
#include <cstdint>

#define N_BANDS    128
#define RESO       64
#define N_FRAMES   128
#define N_SAMPLES  32768
#define BATCH      16
#define N_ROWS     (BATCH * N_BANDS)

typedef unsigned long long u64;

// Pre-duplicated frames: g_framesd[f*2048 + c*16 + b] = (v, v) packed in u64.
__device__ u64 g_framesd[N_FRAMES * N_ROWS];

__device__ __forceinline__ u64 fma2(u64 a, u64 b, u64 c) {
    u64 d;
    asm("fma.rn.f32x2 %0, %1, %2, %3;" : "=l"(d) : "l"(a), "l"(b), "l"(c));
    return d;
}
__device__ __forceinline__ u64 add2(u64 a, u64 b) {
    u64 d;
    asm("add.rn.f32x2 %0, %1, %2;" : "=l"(d) : "l"(a), "l"(b));
    return d;
}
__device__ __forceinline__ u64 sub2(u64 a, u64 b) {
    u64 d;
    asm("sub.rn.f32x2 %0, %1, %2;" : "=l"(d) : "l"(a), "l"(b));
    return d;
}
__device__ __forceinline__ u64 mul2(u64 a, u64 b) {
    u64 d;
    asm("mul.rn.f32x2 %0, %1, %2;" : "=l"(d) : "l"(a), "l"(b));
    return d;
}
__device__ __forceinline__ u64 pack2(float lo, float hi) {
    u64 r;
    asm("mov.b64 %0, {%1, %2};" : "=l"(r) : "f"(lo), "f"(hi));
    return r;
}
__device__ __forceinline__ float u64lo(u64 v) {
    return __uint_as_float((unsigned int)(v & 0xFFFFFFFFull));
}
__device__ __forceinline__ float u64hi(u64 v) {
    return __uint_as_float((unsigned int)(v >> 32));
}

// ---------------------------------------------------------------------------
// Kernel 1: frames = softmax(x) @ resonance, stored transposed + duplicated:
//   g_framesd[f][c][b] = (v,v) u64,  v = frames[b,c,f]
// ---------------------------------------------------------------------------
__global__ __launch_bounds__(256)
void frames_kernel(const float* __restrict__ x,
                   const float* __restrict__ reso) {
    __shared__ float res_s[RESO][N_FRAMES];
    __shared__ float xs[16][RESO];
    __shared__ float ps[16][RESO + 1];

    const int tid = threadIdx.x;
    const int rowbase = blockIdx.x * 16;

    for (int idx = tid; idx < RESO * N_FRAMES; idx += 256)
        res_s[idx >> 7][idx & 127] = reso[idx];
    {
        const float* xb = x + rowbase * RESO;
        for (int idx = tid; idx < 16 * RESO; idx += 256)
            xs[idx >> 6][idx & 63] = xb[idx];
    }
    __syncthreads();

    {
        const int w = tid >> 5;
        const int lane = tid & 31;
        #pragma unroll
        for (int rr = 0; rr < 2; ++rr) {
            const int row = w * 2 + rr;
            float v0 = xs[row][lane];
            float v1 = xs[row][lane + 32];
            float m = fmaxf(v0, v1);
            #pragma unroll
            for (int off = 16; off > 0; off >>= 1)
                m = fmaxf(m, __shfl_xor_sync(0xFFFFFFFFu, m, off));
            float e0 = __expf(v0 - m);
            float e1 = __expf(v1 - m);
            float s = e0 + e1;
            #pragma unroll
            for (int off = 16; off > 0; off >>= 1)
                s += __shfl_xor_sync(0xFFFFFFFFu, s, off);
            float inv = 1.0f / s;
            ps[row][lane]      = e0 * inv;
            ps[row][lane + 32] = e1 * inv;
        }
    }
    __syncthreads();

    {
        const int row_l = tid & 15;
        const int f0 = tid >> 4;
        float acc[8];
        #pragma unroll
        for (int i = 0; i < 8; ++i) acc[i] = 0.0f;
        #pragma unroll 4
        for (int r = 0; r < RESO; ++r) {
            const float pv = ps[row_l][r];
            #pragma unroll
            for (int i = 0; i < 8; ++i)
                acc[i] = fmaf(pv, res_s[r][f0 + 16 * i], acc[i]);
        }
        const int grow = rowbase + row_l;          // row = b*128 + c
        const int b = grow >> 7;
        const int c = grow & 127;
        #pragma unroll
        for (int i = 0; i < 8; ++i) {
            const unsigned int vi = __float_as_uint(acc[i]);
            g_framesd[(f0 + 16 * i) * N_ROWS + c * 16 + b] =
                ((u64)vi << 32) | vi;
        }
    }
}

// ---------------------------------------------------------------------------
// Kernel 2: 512 blocks x 256 threads, 4 blocks/SM. Block n = samples
// [64n, 64n+64); frame pair uniform: i0 = (n<2) ? 0 : (n-2)>>2.
// smem 48KB: F0d/F1d dup'd tables (32KB) + fb ring 2 x 8KB (32 bands each).
// Progressive cp.async: group0 = F + chunk0, group1 = chunk1; chunks 2,3
// staged behind compute in-place.
// Thread (sg 4-samples, bq 4-batches, ih F0/F1, bs 16-band sub-slice):
// per band 1 LDS.128 fb + 2 LDS.128 F + 8 fma2, zero MOVs, 8 u64 accs.
// Epilogue: smem reduce over (ih, bs), interp via f32x2, one STG.128/thread.
// ---------------------------------------------------------------------------
__global__ __launch_bounds__(256, 4)
void mix_kernel(const float* __restrict__ fb,
                float* __restrict__ out) {
    __shared__ __align__(16) float fbbuf[2 * 2048];   // 16 KB ring, 2 chunks
    __shared__ __align__(16) u64 F0d[N_ROWS];         // 16 KB [c*16+b]
    __shared__ __align__(16) u64 F1d[N_ROWS];         // 16 KB

    const int tid = threadIdx.x;
    const int n = blockIdx.x;
    const int s_base = n * 64;

    const int i0 = (n < 2) ? 0 : ((n - 2) >> 2);
    const int i1 = (i0 + 1 < N_FRAMES) ? i0 + 1 : N_FRAMES - 1;

    const unsigned int fb_s0 = (unsigned int)__cvta_generic_to_shared(&fbbuf[0]);
    const unsigned int F0_s0 = (unsigned int)__cvta_generic_to_shared(&F0d[0]);
    const unsigned int F1_s0 = (unsigned int)__cvta_generic_to_shared(&F1d[0]);

    // fb chunk = 32 bands x 64 samples = 8 KB; 2 x 16B per thread.
#define STAGE_FB(CHUNK, BUF)                                                  \
    {                                                                         \
        _Pragma("unroll")                                                     \
        for (int i = 0; i < 2; ++i) {                                         \
            const int o = (i * 256 + tid) * 16;                               \
            const int band = o >> 8;                                          \
            const int within = o & 255;                                       \
            const float* g = fb + ((CHUNK) * 32 + band) * N_SAMPLES           \
                               + s_base + (within >> 2);                      \
            asm volatile("cp.async.cg.shared.global [%0], [%1], 16;\n"        \
                         :: "r"(fb_s0 + (BUF) * 8192 + o), "l"(g));           \
        }                                                                     \
        asm volatile("cp.async.commit_group;\n");                             \
    }

    // Group 0: both F tables + fb chunk 0.  Group 1: fb chunk 1.
    {
        const char* g0 = (const char*)(g_framesd + i0 * N_ROWS);
        const char* g1 = (const char*)(g_framesd + i1 * N_ROWS);
        #pragma unroll
        for (int i = 0; i < 4; ++i) {
            const int o = (i * 256 + tid) * 16;
            asm volatile("cp.async.cg.shared.global [%0], [%1], 16;\n"
                         :: "r"(F0_s0 + o), "l"(g0 + o));
            asm volatile("cp.async.cg.shared.global [%0], [%1], 16;\n"
                         :: "r"(F1_s0 + o), "l"(g1 + o));
        }
        #pragma unroll
        for (int i = 0; i < 2; ++i) {
            const int o = (i * 256 + tid) * 16;
            const int band = o >> 8;
            const int within = o & 255;
            const float* g = fb + band * N_SAMPLES + s_base + (within >> 2);
            asm volatile("cp.async.cg.shared.global [%0], [%1], 16;\n"
                         :: "r"(fb_s0 + o), "l"(g));
        }
        asm volatile("cp.async.commit_group;\n");
    }
    STAGE_FB(1, 1);

    const int sg = tid & 15;             // 4-sample group
    const int bq = (tid >> 4) & 3;       // batch quad (4 batches)
    const int ih = (tid >> 6) & 1;       // 0: F0 dot, 1: F1 dot
    const int bs = tid >> 7;             // 16-band sub-slice within chunk
    const u64* __restrict__ Fd = ih ? F1d : F0d;   // warp-uniform

    u64 acc[4][2];   // [jb][sample-pair]
    #pragma unroll
    for (int jb = 0; jb < 4; ++jb) { acc[jb][0] = 0ull; acc[jb][1] = 0ull; }

#define PROC(BUF, CBASE)                                                      \
    {                                                                         \
        _Pragma("unroll 4")                                                   \
        for (int cl = 0; cl < 16; ++cl) {                                     \
            const int cb = bs * 16 + cl;          /* band within chunk */     \
            const int c  = (CBASE) + cb;                                      \
            const ulonglong2 fp = *reinterpret_cast<const ulonglong2*>(       \
                &fbbuf[(BUF) * 2048 + cb * 64 + sg * 4]);                     \
            const u64* Fr = Fd + c * 16 + bq * 4;                             \
            const ulonglong2 va = *reinterpret_cast<const ulonglong2*>(Fr);   \
            const ulonglong2 vb = *reinterpret_cast<const ulonglong2*>(Fr+2); \
            acc[0][0] = fma2(va.x, fp.x, acc[0][0]);                          \
            acc[0][1] = fma2(va.x, fp.y, acc[0][1]);                          \
            acc[1][0] = fma2(va.y, fp.x, acc[1][0]);                          \
            acc[1][1] = fma2(va.y, fp.y, acc[1][1]);                          \
            acc[2][0] = fma2(vb.x, fp.x, acc[2][0]);                          \
            acc[2][1] = fma2(vb.x, fp.y, acc[2][1]);                          \
            acc[3][0] = fma2(vb.y, fp.x, acc[3][0]);                          \
            acc[3][1] = fma2(vb.y, fp.y, acc[3][1]);                          \
        }                                                                     \
    }

#define WAITG(N) asm volatile("cp.async.wait_group %0;\n" :: "n"(N) : "memory")

    WAITG(1); __syncthreads(); PROC(0, 0);
    __syncthreads(); STAGE_FB(2, 0);
    WAITG(1); __syncthreads(); PROC(1, 32);
    __syncthreads(); STAGE_FB(3, 1);
    WAITG(1); __syncthreads(); PROC(0, 64);
    WAITG(0); __syncthreads(); PROC(1, 96);

#undef STAGE_FB
#undef PROC
#undef WAITG

    // --- Epilogue: reduce over (ih, bs), interp, one STG.128 per thread ---
    __syncthreads();   // all reads of fbbuf done
    u64* S = reinterpret_cast<u64*>(&fbbuf[0]);    // 2048 u64 = 16 KB
    {
        const int slot = ih * 2 + bs;              // 0..3
        #pragma unroll
        for (int jb = 0; jb < 4; ++jb)
            #pragma unroll
            for (int p = 0; p < 2; ++p)
                S[((((slot * 4 + bq) * 4 + jb) * 2) + p) * 16 + sg] =
                    acc[jb][p];
    }
    __syncthreads();

    {
        const int e_sg = tid & 15;
        const int e_b  = tid >> 4;        // batch 0..15
        const int e_bq = e_b >> 2;
        const int e_jb = e_b & 3;
        const int s0 = s_base + e_sg * 4;

        float w[4];
        #pragma unroll
        for (int j = 0; j < 4; ++j) {
            float pos = (float)(s0 + j) * (1.0f / 256.0f)
                        + (0.5f / 256.0f - 0.5f);
            pos = fminf(fmaxf(pos, 0.0f), 127.0f);
            w[j] = pos - floorf(pos);
        }
        const u64 K = pack2(1.0f / 128.0f, 1.0f / 128.0f);

        float4 o;
        float* ov = &o.x;
        #pragma unroll
        for (int p = 0; p < 2; ++p) {
            const int base0 = (((0 * 4 + e_bq) * 4 + e_jb) * 2 + p) * 16 + e_sg;
            const int base1 = (((1 * 4 + e_bq) * 4 + e_jb) * 2 + p) * 16 + e_sg;
            const int base2 = (((2 * 4 + e_bq) * 4 + e_jb) * 2 + p) * 16 + e_sg;
            const int base3 = (((3 * 4 + e_bq) * 4 + e_jb) * 2 + p) * 16 + e_sg;
            const u64 A0 = add2(S[base0], S[base1]);   // ih=0: slots 0,1
            const u64 A1 = add2(S[base2], S[base3]);   // ih=1: slots 2,3
            const u64 wp = pack2(w[2 * p], w[2 * p + 1]);
            const u64 v = mul2(fma2(wp, sub2(A1, A0), A0), K);
            ov[2 * p]     = u64lo(v);
            ov[2 * p + 1] = u64hi(v);
        }
        *reinterpret_cast<float4*>(out + e_b * N_SAMPLES + s0) = o;
    }
}

// ---------------------------------------------------------------------------
extern "C" void kernel_launch(void* const* d_in, const int* in_sizes, int n_in,
                              void* d_out, int out_size) {
    const float* x = nullptr;      // (16,128,64)    = 131072
    const float* reso = nullptr;   // (64,128)       = 8192
    const float* fb = nullptr;     // (1,128,32768)  = 4194304
    for (int i = 0; i < n_in; ++i) {
        if (in_sizes[i] == BATCH * N_BANDS * RESO)      x = (const float*)d_in[i];
        else if (in_sizes[i] == RESO * N_FRAMES)        reso = (const float*)d_in[i];
        else if (in_sizes[i] == N_BANDS * N_SAMPLES)    fb = (const float*)d_in[i];
    }
    float* out = (float*)d_out;

    frames_kernel<<<N_ROWS / 16, 256>>>(x, reso);
    mix_kernel<<<N_SAMPLES / 64, 256>>>(fb, out);
}

// round 8
// speedup vs baseline: 1.4459x; 1.2162x over previous
#include <cuda_runtime.h>
#include <cuda_bf16.h>
#include <cstdint>

#define N_BANDS    128
#define RESO       64
#define N_FRAMES   128
#define N_SAMPLES  32768
#define BATCH      16
#define N_ROWS     (BATCH * N_BANDS)

typedef unsigned long long u64;

// Pair table: g_framep[i*2048 + c*16 + b] = (frames[b,c,i], frames[b,c,min(i+1,127)])
__device__ __align__(16) float2 g_framep[N_FRAMES * N_ROWS];

__device__ __forceinline__ u64 fma2(u64 a, u64 b, u64 c) {
    u64 d;
    asm("fma.rn.f32x2 %0, %1, %2, %3;" : "=l"(d) : "l"(a), "l"(b), "l"(c));
    return d;
}
__device__ __forceinline__ u64 add2(u64 a, u64 b) {
    u64 d;
    asm("add.rn.f32x2 %0, %1, %2;" : "=l"(d) : "l"(a), "l"(b));
    return d;
}
__device__ __forceinline__ u64 dup32(float x) {
    u64 r;
    unsigned int xi = __float_as_uint(x);
    asm("mov.b64 %0, {%1, %1};" : "=l"(r) : "r"(xi));
    return r;
}
__device__ __forceinline__ float u64lo(u64 v) {
    return __uint_as_float((unsigned int)(v & 0xFFFFFFFFull));
}
__device__ __forceinline__ float u64hi(u64 v) {
    return __uint_as_float((unsigned int)(v >> 32));
}

// ---------------------------------------------------------------------------
// Kernel 1: 128 blocks (block = band index c) x 256 threads.
// Block handles rows {b*128 + c : b = 0..15}. Computes softmax + matmul with
// f32x2 over r-pairs, then writes the (f_i, f_{i+1}) pair table COALESCED.
// ---------------------------------------------------------------------------
__global__ __launch_bounds__(256)
void frames_kernel(const float* __restrict__ x,
                   const float* __restrict__ reso) {
    __shared__ float resT[N_FRAMES * 66];   // [f][r] padded stride 66 (33.8KB)
    __shared__ float pool2[2080];           // xs[1024] | ps[16*66]; fr aliases

    float* xs = pool2;                 // [b*64 + r]
    float* ps = pool2 + 1024;          // [b*66 + r]
    float* fr = pool2;                 // [f*16 + b] (after sync, aliases xs/ps)

    const int tid = threadIdx.x;
    const int c = blockIdx.x;

    // Stage resonance transposed: resT[f*66 + r] = reso[r*128 + f]
    for (int idx = tid; idx < RESO * N_FRAMES; idx += 256) {
        const int r = idx >> 7;
        const int f = idx & 127;
        resT[f * 66 + r] = reso[idx];
    }
    // Stage x rows (b = 0..15 at fixed c), 256B segments.
    for (int idx = tid; idx < 16 * RESO; idx += 256) {
        const int b = idx >> 6;
        const int r = idx & 63;
        xs[idx] = x[(b * 128 + c) * RESO + r];
    }
    __syncthreads();

    // Softmax: warp w handles rows 2w, 2w+1.
    {
        const int w = tid >> 5;
        const int lane = tid & 31;
        #pragma unroll
        for (int rr = 0; rr < 2; ++rr) {
            const int row = w * 2 + rr;
            float v0 = xs[row * 64 + lane];
            float v1 = xs[row * 64 + lane + 32];
            float m = fmaxf(v0, v1);
            #pragma unroll
            for (int off = 16; off > 0; off >>= 1)
                m = fmaxf(m, __shfl_xor_sync(0xFFFFFFFFu, m, off));
            float e0 = __expf(v0 - m);
            float e1 = __expf(v1 - m);
            float s = e0 + e1;
            #pragma unroll
            for (int off = 16; off > 0; off >>= 1)
                s += __shfl_xor_sync(0xFFFFFFFFu, s, off);
            float inv = 1.0f / s;
            ps[row * 66 + lane]      = e0 * inv;
            ps[row * 66 + lane + 32] = e1 * inv;
        }
    }
    __syncthreads();

    // Matmul with f32x2 over r-pairs: thread (b = tid&15, f0 = tid>>4).
    float v[8];
    {
        const int b  = tid & 15;
        const int f0 = tid >> 4;
        u64 acc2[8];
        #pragma unroll
        for (int i = 0; i < 8; ++i) acc2[i] = 0ull;

        #pragma unroll 4
        for (int rr = 0; rr < RESO / 2; ++rr) {
            const u64 psp =
                *reinterpret_cast<const u64*>(&ps[b * 66 + 2 * rr]);
            #pragma unroll
            for (int i = 0; i < 8; ++i) {
                const u64 rp = *reinterpret_cast<const u64*>(
                    &resT[(f0 + 16 * i) * 66 + 2 * rr]);
                acc2[i] = fma2(rp, psp, acc2[i]);
            }
        }
        #pragma unroll
        for (int i = 0; i < 8; ++i) v[i] = u64lo(acc2[i]) + u64hi(acc2[i]);
    }
    __syncthreads();   // ps/xs dead; fr may now overwrite pool2

    {
        const int b  = tid & 15;
        const int f0 = tid >> 4;
        #pragma unroll
        for (int i = 0; i < 8; ++i)
            fr[(f0 + 16 * i) * 16 + b] = v[i];
    }
    __syncthreads();

    // Write pair table coalesced: pairs i = f0+16k, neighbors from fr.
    {
        const int b  = tid & 15;
        const int f0 = tid >> 4;
        #pragma unroll
        for (int k = 0; k < 8; ++k) {
            const int p = f0 + 16 * k;
            const int pn = (p + 1 < N_FRAMES) ? p + 1 : N_FRAMES - 1;
            const float lo = fr[p * 16 + b];
            const float hi = fr[pn * 16 + b];
            g_framep[p * N_ROWS + c * 16 + b] = make_float2(lo, hi);
        }
    }
}

// ---------------------------------------------------------------------------
// Kernel 2: 512 blocks x 256 threads. Block n = samples [64n, 64n+64).
// f32x2 lanes = (F0-dot, F1-dot). smem 32KB: FP pair table (16KB) + fb ring
// 2x8KB. Thread: sg = tid&15 (4 samples), bq = (tid>>4)&7 (2 batches),
// bs = tid>>7 (64-band half).
// Per band: 1 LDS.128 fb + 4 dup MOV + 1 LDS.128 FP + 8 fma2.
// Epilogue: 2-way bs reduce via smem, thread-local interp, 2 STG.128.
// ---------------------------------------------------------------------------
__global__ __launch_bounds__(256, 5)
void mix_kernel(const float* __restrict__ fb,
                float* __restrict__ out) {
    __shared__ __align__(16) float fbbuf[2 * 2048];   // 16 KB ring
    __shared__ __align__(16) u64 FPs[N_ROWS];         // 16 KB pair table

    const int tid = threadIdx.x;
    const int n = blockIdx.x;
    const int s_base = n * 64;

    const int i0 = (n < 2) ? 0 : ((n - 2) >> 2);

    const unsigned int fb_s0 = (unsigned int)__cvta_generic_to_shared(&fbbuf[0]);
    const unsigned int FP_s0 = (unsigned int)__cvta_generic_to_shared(&FPs[0]);

#define STAGE_FB(CHUNK, BUF)                                                  \
    {                                                                         \
        _Pragma("unroll")                                                     \
        for (int i = 0; i < 2; ++i) {                                         \
            const int o = (i * 256 + tid) * 16;                               \
            const int band = o >> 8;                                          \
            const int within = o & 255;                                       \
            const float* g = fb + ((CHUNK) * 32 + band) * N_SAMPLES           \
                               + s_base + (within >> 2);                      \
            asm volatile("cp.async.cg.shared.global [%0], [%1], 16;\n"        \
                         :: "r"(fb_s0 + (BUF) * 8192 + o), "l"(g));           \
        }                                                                     \
        asm volatile("cp.async.commit_group;\n");                             \
    }

    // Group 0: FP pair table (16KB) + fb chunk 0.  Group 1: chunk 1.
    {
        const char* gp = (const char*)(g_framep + i0 * N_ROWS);
        #pragma unroll
        for (int i = 0; i < 4; ++i) {
            const int o = (i * 256 + tid) * 16;
            asm volatile("cp.async.cg.shared.global [%0], [%1], 16;\n"
                         :: "r"(FP_s0 + o), "l"(gp + o));
        }
        #pragma unroll
        for (int i = 0; i < 2; ++i) {
            const int o = (i * 256 + tid) * 16;
            const int band = o >> 8;
            const int within = o & 255;
            const float* g = fb + band * N_SAMPLES + s_base + (within >> 2);
            asm volatile("cp.async.cg.shared.global [%0], [%1], 16;\n"
                         :: "r"(fb_s0 + o), "l"(g));
        }
        asm volatile("cp.async.commit_group;\n");
    }
    STAGE_FB(1, 1);

    const int sg = tid & 15;             // 4-sample group
    const int bq = (tid >> 4) & 7;       // batch pair (batches 2bq, 2bq+1)
    const int bs = tid >> 7;             // band half (64 bands)

    u64 acc[8];   // acc[bp*4+j]: batch 2bq+bp, sample j; lanes (dot0, dot1)
    #pragma unroll
    for (int p = 0; p < 8; ++p) acc[p] = 0ull;

#define PROC(BUF, CH)                                                         \
    {                                                                         \
        _Pragma("unroll 4")                                                   \
        for (int cl = 0; cl < 16; ++cl) {                                     \
            const int cb = bs * 16 + cl;                                      \
            const int c  = (CH) * 32 + cb;                                    \
            const float4 fv = *reinterpret_cast<const float4*>(               \
                &fbbuf[(BUF) * 2048 + cb * 64 + sg * 4]);                     \
            const u64 d0 = dup32(fv.x);                                       \
            const u64 d1 = dup32(fv.y);                                       \
            const u64 d2 = dup32(fv.z);                                       \
            const u64 d3 = dup32(fv.w);                                       \
            const ulonglong2 fp2 = *reinterpret_cast<const ulonglong2*>(      \
                &FPs[c * 16 + bq * 2]);                                       \
            acc[0] = fma2(fp2.x, d0, acc[0]);                                 \
            acc[1] = fma2(fp2.x, d1, acc[1]);                                 \
            acc[2] = fma2(fp2.x, d2, acc[2]);                                 \
            acc[3] = fma2(fp2.x, d3, acc[3]);                                 \
            acc[4] = fma2(fp2.y, d0, acc[4]);                                 \
            acc[5] = fma2(fp2.y, d1, acc[5]);                                 \
            acc[6] = fma2(fp2.y, d2, acc[6]);                                 \
            acc[7] = fma2(fp2.y, d3, acc[7]);                                 \
        }                                                                     \
    }

#define WAITG(N) asm volatile("cp.async.wait_group %0;\n" :: "n"(N) : "memory")

    WAITG(1); __syncthreads(); PROC(0, 0);
    __syncthreads(); STAGE_FB(2, 0);
    WAITG(1); __syncthreads(); PROC(1, 1);
    __syncthreads(); STAGE_FB(3, 1);
    WAITG(1); __syncthreads(); PROC(0, 2);
    WAITG(0); __syncthreads(); PROC(1, 3);

#undef STAGE_FB
#undef PROC
#undef WAITG

    // --- Epilogue: reduce over bs (2 halves), interp locally, store ---
    __syncthreads();   // all reads of fbbuf done
    u64* S = reinterpret_cast<u64*>(&fbbuf[0]);    // 2048 u64 capacity
    if (tid >= 128) {
        const int j = tid - 128;
        #pragma unroll
        for (int p = 0; p < 8; ++p) S[j * 9 + p] = acc[p];
    }
    __syncthreads();
    if (tid < 128) {
        const int s0 = s_base + sg * 4;
        float w[4];
        #pragma unroll
        for (int j = 0; j < 4; ++j) {
            float pos = (float)(s0 + j) * (1.0f / 256.0f)
                        + (0.5f / 256.0f - 0.5f);
            pos = fminf(fmaxf(pos, 0.0f), 127.0f);
            w[j] = pos - floorf(pos);
        }
        #pragma unroll
        for (int bp = 0; bp < 2; ++bp) {
            float4 o;
            float* ov = &o.x;
            #pragma unroll
            for (int j = 0; j < 4; ++j) {
                const u64 A = add2(acc[bp * 4 + j], S[tid * 9 + bp * 4 + j]);
                const float a0 = u64lo(A);
                const float a1 = u64hi(A);
                ov[j] = fmaf(w[j], a1 - a0, a0) * (1.0f / 128.0f);
            }
            *reinterpret_cast<float4*>(
                out + (bq * 2 + bp) * N_SAMPLES + s0) = o;
        }
    }
}

// ---------------------------------------------------------------------------
extern "C" void kernel_launch(void* const* d_in, const int* in_sizes, int n_in,
                              void* d_out, int out_size) {
    const float* x = nullptr;      // (16,128,64)    = 131072
    const float* reso = nullptr;   // (64,128)       = 8192
    const float* fb = nullptr;     // (1,128,32768)  = 4194304
    for (int i = 0; i < n_in; ++i) {
        if (in_sizes[i] == BATCH * N_BANDS * RESO)      x = (const float*)d_in[i];
        else if (in_sizes[i] == RESO * N_FRAMES)        reso = (const float*)d_in[i];
        else if (in_sizes[i] == N_BANDS * N_SAMPLES)    fb = (const float*)d_in[i];
    }
    float* out = (float*)d_out;

    frames_kernel<<<N_BANDS, 256>>>(x, reso);
    mix_kernel<<<N_SAMPLES / 64, 256>>>(fb, out);
}